// round 6
// baseline (speedup 1.0000x reference)
#include <cuda_runtime.h>
#include <math.h>

#define TT 6
#define NN 50000
#define EE 800000
#define FF 32
#define HH 64
#define OUTC 16
#define SPAD 68

#define TOTN (TT * NN)                 // 300000
#define SCAN_BLOCKS 1172               // ceil(TOTN/256)
#define AUX_PER_THREAD 5               // 256*5 = 1280 >= 1172
#define DEG_BPS   3125                 // EE/256
#define PLACE_BPS 3125

typedef unsigned long long u64;
#define FMA_F32X2(d, a, b, c) \
    asm("fma.rn.f32x2 %0, %1, %2, %3;" : "=l"(d) : "l"(a), "l"(b), "l"(c))

// ---------------- scratch (device globals; no allocation allowed) ----------
__device__ __align__(16) float g_aggx[(size_t)TT * NN * FF];  // A_hat@X, all steps
__device__ __align__(16) float g_h   [(size_t)NN * HH];
__device__ int   g_deg [TOTN];
__device__ int   g_roff[TOTN];
__device__ int   g_cur [TOTN];
__device__ int   g_bsum[SCAN_BLOCKS];
__device__ int   g_csr [(size_t)TT * EE];
__device__ float g_dinv[TOTN];

// folded weights, entries DUPLICATED as (w,w) pairs for f32x2 FFMA2
__device__ __align__(16) float g_MtD [3][HH][FF * 2];  // (W @ L_top)^T dup
__device__ __align__(16) float g_LbtD[3][HH][HH * 2];  // L_bot^T dup
__device__ float g_bv[3][HH];

__device__ __forceinline__ float sigmoidf_(float x) {
    return 1.0f / (1.0f + __expf(-x));
}

// ---------------- prep / clears ---------------------------------------------

__global__ void k_clear_h() {
    unsigned idx = blockIdx.x * blockDim.x + threadIdx.x;
    if (idx < (unsigned)(NN * HH)) g_h[idx] = 0.0f;
}

__global__ void k_clear_int2() {
    unsigned i = blockIdx.x * blockDim.x + threadIdx.x;
    if (i < (unsigned)TOTN) { g_deg[i] = 0; g_cur[i] = 0; }
}

__global__ void k_prep(const float* __restrict__ Wz, const float* __restrict__ bz,
                       const float* __restrict__ Wr, const float* __restrict__ br,
                       const float* __restrict__ Wh, const float* __restrict__ bh,
                       const float* __restrict__ Lz, const float* __restrict__ Lzb,
                       const float* __restrict__ Lr, const float* __restrict__ Lrb,
                       const float* __restrict__ Lh, const float* __restrict__ Lhb) {
    int g = blockIdx.x;
    int t = threadIdx.x;
    const float* W  = (g == 0) ? Wz  : (g == 1) ? Wr  : Wh;
    const float* b  = (g == 0) ? bz  : (g == 1) ? br  : bh;
    const float* L  = (g == 0) ? Lz  : (g == 1) ? Lr  : Lh;
    const float* Lb = (g == 0) ? Lzb : (g == 1) ? Lrb : Lhb;

    for (int e = t; e < HH * FF; e += 256) {
        int j = e >> 5, f = e & 31;
        float s = 0.f;
        #pragma unroll 8
        for (int m = 0; m < HH; m++) s += __ldg(W + f * HH + m) * __ldg(L + m * HH + j);
        g_MtD[g][j][2 * f]     = s;
        g_MtD[g][j][2 * f + 1] = s;
    }
    for (int e = t; e < HH * HH; e += 256) {
        int j = e >> 6, k = e & 63;
        float v = __ldg(L + (HH + k) * HH + j);
        g_LbtD[g][j][2 * k]     = v;
        g_LbtD[g][j][2 * k + 1] = v;
    }
    if (t < HH) {
        float sb = __ldg(Lb + t);
        #pragma unroll 8
        for (int m = 0; m < HH; m++) sb += __ldg(b + m) * __ldg(L + m * HH + t);
        g_bv[g][t] = sb;
    }
}

// ---------------- degree + dinv ----------------------------------------------

__global__ void k_deg_all(const int* __restrict__ ei) {
    int t = blockIdx.x / DEG_BPS;
    unsigned e = (blockIdx.x % DEG_BPS) * 256 + threadIdx.x;
    int d = __ldg(ei + (size_t)t * 2 * EE + EE + e);
    atomicAdd(&g_deg[t * NN + d], 1);
}

__global__ void k_dinv_all() {
    unsigned i = blockIdx.x * blockDim.x + threadIdx.x;
    if (i < (unsigned)TOTN) g_dinv[i] = rsqrtf((float)(g_deg[i] + 1));
}

// ---------------- exclusive scan ----------------------------------------------

__global__ void k_scan_block() {
    __shared__ int sh[256];
    int tid = threadIdx.x;
    int i = blockIdx.x * 256 + tid;
    int v = (i < TOTN) ? g_deg[i] : 0;
    sh[tid] = v;
    __syncthreads();
    #pragma unroll
    for (int off = 1; off < 256; off <<= 1) {
        int tv = (tid >= off) ? sh[tid - off] : 0;
        __syncthreads();
        sh[tid] += tv;
        __syncthreads();
    }
    if (i < TOTN) g_roff[i] = sh[tid] - v;
    if (tid == 255) g_bsum[blockIdx.x] = sh[255];
}

__global__ void k_scan_aux() {
    __shared__ int part[256];
    int tid = threadIdx.x;
    int start = tid * AUX_PER_THREAD;
    int loc[AUX_PER_THREAD];
    int vv [AUX_PER_THREAD];
    int sum = 0;
    #pragma unroll
    for (int j = 0; j < AUX_PER_THREAD; j++) {
        int idx = start + j;
        int v = (idx < SCAN_BLOCKS) ? g_bsum[idx] : 0;
        vv[j] = v;
        sum += v;
        loc[j] = sum;
    }
    part[tid] = sum;
    __syncthreads();
    #pragma unroll
    for (int off = 1; off < 256; off <<= 1) {
        int tv = (tid >= off) ? part[tid - off] : 0;
        __syncthreads();
        part[tid] += tv;
        __syncthreads();
    }
    int prev = (tid > 0) ? part[tid - 1] : 0;
    #pragma unroll
    for (int j = 0; j < AUX_PER_THREAD; j++) {
        int idx = start + j;
        if (idx < SCAN_BLOCKS) g_bsum[idx] = prev + loc[j] - vv[j];
    }
}

__global__ void k_scan_add() {
    int i = blockIdx.x * 256 + threadIdx.x;
    if (i < TOTN) g_roff[i] += g_bsum[blockIdx.x];
}

// ---------------- CSR placement ----------------------------------------------

__global__ void k_place(const int* __restrict__ ei) {
    int t = blockIdx.x / PLACE_BPS;
    unsigned e = (blockIdx.x % PLACE_BPS) * 256 + threadIdx.x;
    const int* base = ei + (size_t)t * 2 * EE;
    int s = __ldg(base + e);
    int d = __ldg(base + EE + e);
    int i = t * NN + d;
    int pos = g_roff[i] + atomicAdd(&g_cur[i], 1);
    g_csr[pos] = s;
}

// ---------------- pull gather: warp per (t,node), lane = feature ------------

__global__ void __launch_bounds__(256) k_gather(const float* __restrict__ xs) {
    int gw = (blockIdx.x * blockDim.x + threadIdx.x) >> 5;
    int lane = threadIdx.x & 31;
    if (gw >= TOTN) return;
    int t = gw / NN;
    int node = gw - t * NN;
    const float* x = xs + (size_t)t * NN * FF;
    const float* dinv_t = g_dinv + t * NN;

    float dd = g_dinv[gw];
    float acc = __ldg(x + (size_t)node * FF + lane) * dd * dd;  // self loop

    int beg = g_roff[gw];
    int deg = g_deg[gw];
    for (int base = 0; base < deg; base += 32) {
        int p = base + lane;
        int sidx = 0;
        float wt = 0.f;
        if (p < deg) {
            sidx = __ldg(g_csr + beg + p);
            wt = dd * __ldg(dinv_t + sidx);
        }
        #pragma unroll
        for (int e = 0; e < 32; e++) {
            int   s = __shfl_sync(0xffffffffu, sidx, e);
            float w = __shfl_sync(0xffffffffu, wt, e);
            acc = fmaf(__ldg(x + (size_t)s * FF + lane), w, acc);
        }
    }
    g_aggx[(size_t)gw * FF + lane] = acc;
}

// ---------------- fused projection + GRU gates (f32x2 / FFMA2) --------------

__global__ void __launch_bounds__(256) k_gates2(int t) {
    __shared__ float ag_sh[FF][SPAD];
    __shared__ float h_sh [HH][SPAD];
    __shared__ float hr_sh[HH][SPAD];

    int tid = threadIdx.x;
    int block_base = blockIdx.x * 64;
    const float* aggx_t = g_aggx + (size_t)t * NN * FF;

    #pragma unroll
    for (int r = 0; r < 2; r++) {
        int idx = r * 256 + tid;
        int n = idx >> 3, k4 = idx & 7;
        int node = block_base + n;
        float4 v = make_float4(0.f, 0.f, 0.f, 0.f);
        if (node < NN) v = __ldg(reinterpret_cast<const float4*>(aggx_t + (size_t)node * FF) + k4);
        ag_sh[k4 * 4 + 0][n] = v.x;
        ag_sh[k4 * 4 + 1][n] = v.y;
        ag_sh[k4 * 4 + 2][n] = v.z;
        ag_sh[k4 * 4 + 3][n] = v.w;
    }
    #pragma unroll
    for (int r = 0; r < 4; r++) {
        int idx = r * 256 + tid;
        int n = idx >> 4, k4 = idx & 15;
        int node = block_base + n;
        float4 v = make_float4(0.f, 0.f, 0.f, 0.f);
        if (node < NN) v = __ldg(reinterpret_cast<const float4*>(g_h + (size_t)node * HH) + k4);
        h_sh[k4 * 4 + 0][n] = v.x;
        h_sh[k4 * 4 + 1][n] = v.y;
        h_sh[k4 * 4 + 2][n] = v.z;
        h_sh[k4 * 4 + 3][n] = v.w;
    }
    __syncthreads();

    int warp = tid >> 5, lane = tid & 31;
    int nb = warp * 8;
    int j0 = lane, j1 = lane + 32;

    u64 az0[4], az1[4], ar0[4], ar1[4];
    #pragma unroll
    for (int q = 0; q < 4; q++) { az0[q] = az1[q] = ar0[q] = ar1[q] = 0ULL; }

    // z/r over aggx (FF ks) — weights duplicated: float4 covers 2 ks
    #pragma unroll
    for (int k2 = 0; k2 < FF / 2; k2++) {
        float4 wz0v = __ldg(reinterpret_cast<const float4*>(&g_MtD[0][j0][k2 * 4]));
        float4 wz1v = __ldg(reinterpret_cast<const float4*>(&g_MtD[0][j1][k2 * 4]));
        float4 wr0v = __ldg(reinterpret_cast<const float4*>(&g_MtD[1][j0][k2 * 4]));
        float4 wr1v = __ldg(reinterpret_cast<const float4*>(&g_MtD[1][j1][k2 * 4]));
        const u64* wz0p = (const u64*)&wz0v; const u64* wz1p = (const u64*)&wz1v;
        const u64* wr0p = (const u64*)&wr0v; const u64* wr1p = (const u64*)&wr1v;
        #pragma unroll
        for (int kk = 0; kk < 2; kk++) {
            int k = k2 * 2 + kk;
            const u64* a01 = (const u64*)&ag_sh[k][nb];
            const u64* a23 = (const u64*)&ag_sh[k][nb + 4];
            u64 aa[4] = {a01[0], a01[1], a23[0], a23[1]};
            #pragma unroll
            for (int q = 0; q < 4; q++) {
                FMA_F32X2(az0[q], aa[q], wz0p[kk], az0[q]);
                FMA_F32X2(az1[q], aa[q], wz1p[kk], az1[q]);
                FMA_F32X2(ar0[q], aa[q], wr0p[kk], ar0[q]);
                FMA_F32X2(ar1[q], aa[q], wr1p[kk], ar1[q]);
            }
        }
    }
    // z/r over h (HH ks)
    #pragma unroll
    for (int k2 = 0; k2 < HH / 2; k2++) {
        float4 wz0v = __ldg(reinterpret_cast<const float4*>(&g_LbtD[0][j0][k2 * 4]));
        float4 wz1v = __ldg(reinterpret_cast<const float4*>(&g_LbtD[0][j1][k2 * 4]));
        float4 wr0v = __ldg(reinterpret_cast<const float4*>(&g_LbtD[1][j0][k2 * 4]));
        float4 wr1v = __ldg(reinterpret_cast<const float4*>(&g_LbtD[1][j1][k2 * 4]));
        const u64* wz0p = (const u64*)&wz0v; const u64* wz1p = (const u64*)&wz1v;
        const u64* wr0p = (const u64*)&wr0v; const u64* wr1p = (const u64*)&wr1v;
        #pragma unroll
        for (int kk = 0; kk < 2; kk++) {
            int k = k2 * 2 + kk;
            const u64* a01 = (const u64*)&h_sh[k][nb];
            const u64* a23 = (const u64*)&h_sh[k][nb + 4];
            u64 aa[4] = {a01[0], a01[1], a23[0], a23[1]};
            #pragma unroll
            for (int q = 0; q < 4; q++) {
                FMA_F32X2(az0[q], aa[q], wz0p[kk], az0[q]);
                FMA_F32X2(az1[q], aa[q], wz1p[kk], az1[q]);
                FMA_F32X2(ar0[q], aa[q], wr0p[kk], ar0[q]);
                FMA_F32X2(ar1[q], aa[q], wr1p[kk], ar1[q]);
            }
        }
    }

    float bvz0 = __ldg(&g_bv[0][j0]), bvz1 = __ldg(&g_bv[0][j1]);
    float bvr0 = __ldg(&g_bv[1][j0]), bvr1 = __ldg(&g_bv[1][j1]);

    float Z0a[8], Z1a[8];
    #pragma unroll
    for (int q = 0; q < 4; q++) {
        float z0lo = __uint_as_float((unsigned)(az0[q] & 0xffffffffULL));
        float z0hi = __uint_as_float((unsigned)(az0[q] >> 32));
        float z1lo = __uint_as_float((unsigned)(az1[q] & 0xffffffffULL));
        float z1hi = __uint_as_float((unsigned)(az1[q] >> 32));
        float r0lo = __uint_as_float((unsigned)(ar0[q] & 0xffffffffULL));
        float r0hi = __uint_as_float((unsigned)(ar0[q] >> 32));
        float r1lo = __uint_as_float((unsigned)(ar1[q] & 0xffffffffULL));
        float r1hi = __uint_as_float((unsigned)(ar1[q] >> 32));
        int n0 = q * 2, n1 = q * 2 + 1;
        Z0a[n0] = sigmoidf_(z0lo + bvz0);  Z0a[n1] = sigmoidf_(z0hi + bvz0);
        Z1a[n0] = sigmoidf_(z1lo + bvz1);  Z1a[n1] = sigmoidf_(z1hi + bvz1);
        float R00 = sigmoidf_(r0lo + bvr0), R01 = sigmoidf_(r0hi + bvr0);
        float R10 = sigmoidf_(r1lo + bvr1), R11 = sigmoidf_(r1hi + bvr1);
        hr_sh[j0][nb + n0] = h_sh[j0][nb + n0] * R00;
        hr_sh[j0][nb + n1] = h_sh[j0][nb + n1] * R01;
        hr_sh[j1][nb + n0] = h_sh[j1][nb + n0] * R10;
        hr_sh[j1][nb + n1] = h_sh[j1][nb + n1] * R11;
    }
    __syncwarp();

    // h gate
    u64 ah0[4], ah1[4];
    #pragma unroll
    for (int q = 0; q < 4; q++) { ah0[q] = ah1[q] = 0ULL; }

    #pragma unroll
    for (int k2 = 0; k2 < FF / 2; k2++) {
        float4 wh0v = __ldg(reinterpret_cast<const float4*>(&g_MtD[2][j0][k2 * 4]));
        float4 wh1v = __ldg(reinterpret_cast<const float4*>(&g_MtD[2][j1][k2 * 4]));
        const u64* wh0p = (const u64*)&wh0v; const u64* wh1p = (const u64*)&wh1v;
        #pragma unroll
        for (int kk = 0; kk < 2; kk++) {
            int k = k2 * 2 + kk;
            const u64* a01 = (const u64*)&ag_sh[k][nb];
            const u64* a23 = (const u64*)&ag_sh[k][nb + 4];
            u64 aa[4] = {a01[0], a01[1], a23[0], a23[1]};
            #pragma unroll
            for (int q = 0; q < 4; q++) {
                FMA_F32X2(ah0[q], aa[q], wh0p[kk], ah0[q]);
                FMA_F32X2(ah1[q], aa[q], wh1p[kk], ah1[q]);
            }
        }
    }
    #pragma unroll
    for (int k2 = 0; k2 < HH / 2; k2++) {
        float4 wh0v = __ldg(reinterpret_cast<const float4*>(&g_LbtD[2][j0][k2 * 4]));
        float4 wh1v = __ldg(reinterpret_cast<const float4*>(&g_LbtD[2][j1][k2 * 4]));
        const u64* wh0p = (const u64*)&wh0v; const u64* wh1p = (const u64*)&wh1v;
        #pragma unroll
        for (int kk = 0; kk < 2; kk++) {
            int k = k2 * 2 + kk;
            const u64* a01 = (const u64*)&hr_sh[k][nb];
            const u64* a23 = (const u64*)&hr_sh[k][nb + 4];
            u64 aa[4] = {a01[0], a01[1], a23[0], a23[1]};
            #pragma unroll
            for (int q = 0; q < 4; q++) {
                FMA_F32X2(ah0[q], aa[q], wh0p[kk], ah0[q]);
                FMA_F32X2(ah1[q], aa[q], wh1p[kk], ah1[q]);
            }
        }
    }

    float bvh0 = __ldg(&g_bv[2][j0]), bvh1 = __ldg(&g_bv[2][j1]);
    #pragma unroll
    for (int q = 0; q < 4; q++) {
        float h0lo = __uint_as_float((unsigned)(ah0[q] & 0xffffffffULL));
        float h0hi = __uint_as_float((unsigned)(ah0[q] >> 32));
        float h1lo = __uint_as_float((unsigned)(ah1[q] & 0xffffffffULL));
        float h1hi = __uint_as_float((unsigned)(ah1[q] >> 32));
        int nn0 = q * 2, nn1 = q * 2 + 1;
        int node0 = block_base + nb + nn0;
        int node1 = block_base + nb + nn1;
        if (node0 < NN) {
            float Ht0 = tanhf(h0lo + bvh0);
            float Ht1 = tanhf(h1lo + bvh1);
            float h0 = h_sh[j0][nb + nn0];
            float h1 = h_sh[j1][nb + nn0];
            g_h[(size_t)node0 * HH + j0] = Z0a[nn0] * h0 + (1.f - Z0a[nn0]) * Ht0;
            g_h[(size_t)node0 * HH + j1] = Z1a[nn0] * h1 + (1.f - Z1a[nn0]) * Ht1;
        }
        if (node1 < NN) {
            float Ht0 = tanhf(h0hi + bvh0);
            float Ht1 = tanhf(h1hi + bvh1);
            float h0 = h_sh[j0][nb + nn1];
            float h1 = h_sh[j1][nb + nn1];
            g_h[(size_t)node1 * HH + j0] = Z0a[nn1] * h0 + (1.f - Z0a[nn1]) * Ht0;
            g_h[(size_t)node1 * HH + j1] = Z1a[nn1] * h1 + (1.f - Z1a[nn1]) * Ht1;
        }
    }
}

__global__ void k_out(const float* __restrict__ oW, const float* __restrict__ ob,
                      float* __restrict__ out) {
    unsigned idx = blockIdx.x * blockDim.x + threadIdx.x;
    if (idx >= (unsigned)(NN * OUTC)) return;
    int i = idx >> 4, j = idx & 15;
    const float* hr = g_h + (size_t)i * HH;
    float acc = __ldg(ob + j);
    #pragma unroll
    for (int k = 0; k < HH; k++) acc += hr[k] * __ldg(oW + k * OUTC + j);
    out[idx] = acc;
}

// ---------------- launch ----------------------------------------------------
extern "C" void kernel_launch(void* const* d_in, const int* in_sizes, int n_in,
                              void* d_out, int out_size) {
    const float* xs  = (const float*)d_in[0];
    const int*   ei  = (const int*)  d_in[1];
    const float* Wz  = (const float*)d_in[2];
    const float* bz  = (const float*)d_in[3];
    const float* Wr  = (const float*)d_in[4];
    const float* br  = (const float*)d_in[5];
    const float* Wh  = (const float*)d_in[6];
    const float* bh  = (const float*)d_in[7];
    const float* Lz  = (const float*)d_in[8];
    const float* Lzb = (const float*)d_in[9];
    const float* Lr  = (const float*)d_in[10];
    const float* Lrb = (const float*)d_in[11];
    const float* Lh  = (const float*)d_in[12];
    const float* Lhb = (const float*)d_in[13];
    const float* oW  = (const float*)d_in[14];
    const float* ob  = (const float*)d_in[15];
    float* out = (float*)d_out;

    k_prep<<<3, 256>>>(Wz, bz, Wr, br, Wh, bh, Lz, Lzb, Lr, Lrb, Lh, Lhb);
    k_clear_h<<<(NN * HH + 255) / 256, 256>>>();
    k_clear_int2<<<SCAN_BLOCKS, 256>>>();

    k_deg_all<<<TT * DEG_BPS, 256>>>(ei);
    k_dinv_all<<<SCAN_BLOCKS, 256>>>();
    k_scan_block<<<SCAN_BLOCKS, 256>>>();
    k_scan_aux<<<1, 256>>>();
    k_scan_add<<<SCAN_BLOCKS, 256>>>();
    k_place<<<TT * PLACE_BPS, 256>>>(ei);
    k_gather<<<(TOTN * 32 + 255) / 256, 256>>>(xs);

    for (int t = 0; t < TT; t++)
        k_gates2<<<(NN + 63) / 64, 256>>>(t);

    k_out<<<(NN * OUTC + 255) / 256, 256>>>(oW, ob, out);
}

// round 7
// speedup vs baseline: 1.5611x; 1.5611x over previous
#include <cuda_runtime.h>
#include <math.h>

#define TT 6
#define NN 50000
#define EE 800000
#define FF 32
#define HH 64
#define OUTC 16
#define SPAD 68

#define TOTN (TT * NN)                 // 300000
#define SCAN_BLOCKS 1172               // ceil(TOTN/256)
#define AUX_PER_THREAD 5               // 256*5 = 1280 >= 1172
#define DEG_BPS   3125                 // EE/256
#define PLACE_BPS 3125
#define GATH_BLOCKS 9375               // TOTN*8/256 exact

typedef unsigned long long u64;

// ---------------- scratch (device globals; no allocation allowed) ----------
__device__ __align__(16) float g_aggx[(size_t)TT * NN * FF];  // A_hat@X, all steps
__device__ __align__(16) float g_h   [(size_t)NN * HH];
__device__ int   g_deg [TOTN];
__device__ int   g_roff[TOTN];
__device__ int   g_cur [TOTN];
__device__ int   g_bsum[SCAN_BLOCKS];
__device__ u64   g_csrp[(size_t)TT * EE];   // packed (src, norm) per edge
__device__ float g_dinv[TOTN];

// folded / transposed weights
__device__ __align__(16) float g_Mt [3][HH][FF];  // (W @ L_top)^T
__device__ __align__(16) float g_Lbt[3][HH][HH];  // L_bot^T
__device__ float g_bv[3][HH];

__device__ __forceinline__ float sigmoidf_(float x) {
    return 1.0f / (1.0f + __expf(-x));
}

// ---------------- prep / clears ---------------------------------------------

__global__ void k_clear_h() {
    unsigned idx = blockIdx.x * blockDim.x + threadIdx.x;
    if (idx < (unsigned)(NN * HH)) g_h[idx] = 0.0f;
}

__global__ void k_clear_int2() {
    unsigned i = blockIdx.x * blockDim.x + threadIdx.x;
    if (i < (unsigned)TOTN) { g_deg[i] = 0; g_cur[i] = 0; }
}

__global__ void k_prep(const float* __restrict__ Wz, const float* __restrict__ bz,
                       const float* __restrict__ Wr, const float* __restrict__ br,
                       const float* __restrict__ Wh, const float* __restrict__ bh,
                       const float* __restrict__ Lz, const float* __restrict__ Lzb,
                       const float* __restrict__ Lr, const float* __restrict__ Lrb,
                       const float* __restrict__ Lh, const float* __restrict__ Lhb) {
    int g = blockIdx.x;
    int t = threadIdx.x;
    const float* W  = (g == 0) ? Wz  : (g == 1) ? Wr  : Wh;
    const float* b  = (g == 0) ? bz  : (g == 1) ? br  : bh;
    const float* L  = (g == 0) ? Lz  : (g == 1) ? Lr  : Lh;
    const float* Lb = (g == 0) ? Lzb : (g == 1) ? Lrb : Lhb;

    for (int e = t; e < HH * FF; e += 256) {
        int j = e >> 5, f = e & 31;
        float s = 0.f;
        #pragma unroll 8
        for (int m = 0; m < HH; m++) s += __ldg(W + f * HH + m) * __ldg(L + m * HH + j);
        g_Mt[g][j][f] = s;
    }
    for (int e = t; e < HH * HH; e += 256) {
        int j = e >> 6, k = e & 63;
        g_Lbt[g][j][k] = __ldg(L + (HH + k) * HH + j);
    }
    if (t < HH) {
        float sb = __ldg(Lb + t);
        #pragma unroll 8
        for (int m = 0; m < HH; m++) sb += __ldg(b + m) * __ldg(L + m * HH + t);
        g_bv[g][t] = sb;
    }
}

// ---------------- degree + dinv ----------------------------------------------

__global__ void k_deg_all(const int* __restrict__ ei) {
    int t = blockIdx.x / DEG_BPS;
    unsigned e = (blockIdx.x % DEG_BPS) * 256 + threadIdx.x;
    int d = __ldg(ei + (size_t)t * 2 * EE + EE + e);
    atomicAdd(&g_deg[t * NN + d], 1);
}

__global__ void k_dinv_all() {
    unsigned i = blockIdx.x * blockDim.x + threadIdx.x;
    if (i < (unsigned)TOTN) g_dinv[i] = rsqrtf((float)(g_deg[i] + 1));
}

// ---------------- exclusive scan ----------------------------------------------

__global__ void k_scan_block() {
    __shared__ int sh[256];
    int tid = threadIdx.x;
    int i = blockIdx.x * 256 + tid;
    int v = (i < TOTN) ? g_deg[i] : 0;
    sh[tid] = v;
    __syncthreads();
    #pragma unroll
    for (int off = 1; off < 256; off <<= 1) {
        int tv = (tid >= off) ? sh[tid - off] : 0;
        __syncthreads();
        sh[tid] += tv;
        __syncthreads();
    }
    if (i < TOTN) g_roff[i] = sh[tid] - v;
    if (tid == 255) g_bsum[blockIdx.x] = sh[255];
}

__global__ void k_scan_aux() {
    __shared__ int part[256];
    int tid = threadIdx.x;
    int start = tid * AUX_PER_THREAD;
    int loc[AUX_PER_THREAD];
    int vv [AUX_PER_THREAD];
    int sum = 0;
    #pragma unroll
    for (int j = 0; j < AUX_PER_THREAD; j++) {
        int idx = start + j;
        int v = (idx < SCAN_BLOCKS) ? g_bsum[idx] : 0;
        vv[j] = v;
        sum += v;
        loc[j] = sum;
    }
    part[tid] = sum;
    __syncthreads();
    #pragma unroll
    for (int off = 1; off < 256; off <<= 1) {
        int tv = (tid >= off) ? part[tid - off] : 0;
        __syncthreads();
        part[tid] += tv;
        __syncthreads();
    }
    int prev = (tid > 0) ? part[tid - 1] : 0;
    #pragma unroll
    for (int j = 0; j < AUX_PER_THREAD; j++) {
        int idx = start + j;
        if (idx < SCAN_BLOCKS) g_bsum[idx] = prev + loc[j] - vv[j];
    }
}

__global__ void k_scan_add() {
    int i = blockIdx.x * 256 + threadIdx.x;
    if (i < TOTN) g_roff[i] += g_bsum[blockIdx.x];
}

// ---------------- CSR placement (packed src + norm) --------------------------

__global__ void k_place(const int* __restrict__ ei) {
    int t = blockIdx.x / PLACE_BPS;
    unsigned e = (blockIdx.x % PLACE_BPS) * 256 + threadIdx.x;
    const int* base = ei + (size_t)t * 2 * EE;
    int s = __ldg(base + e);
    int d = __ldg(base + EE + e);
    int i = t * NN + d;
    int pos = g_roff[i] + atomicAdd(&g_cur[i], 1);
    float w = __ldg(&g_dinv[t * NN + s]) * __ldg(&g_dinv[i]);
    g_csrp[pos] = (u64)(unsigned)s | ((u64)__float_as_uint(w) << 32);
}

// ---------------- pull gather: 8 lanes per node, lane = float4-chunk --------
// Each round: 8 lanes load 8 consecutive packed edge records (coalesced),
// shfl-broadcast within the group, jointly load the full 128B source row.

__global__ void __launch_bounds__(256) k_gather(const float* __restrict__ xs) {
    int gid = blockIdx.x * 256 + threadIdx.x;     // grid exact: TOTN*8 threads
    int gnode = gid >> 3;                          // flat (t,node)
    int chunk = gid & 7;
    int t = gnode / NN;
    int node = gnode - t * NN;
    const float* x = xs + (size_t)t * NN * FF;

    float dd = g_dinv[gnode];
    float4 acc = __ldg(reinterpret_cast<const float4*>(x + (size_t)node * FF) + chunk);
    float d2 = dd * dd;
    acc.x *= d2; acc.y *= d2; acc.z *= d2; acc.w *= d2;

    int beg = g_roff[gnode];
    int deg = g_deg[gnode];
    for (int base = 0; base < deg; base += 8) {
        int p = base + chunk;
        int s = 0; float w = 0.f;
        if (p < deg) {
            u64 rec = __ldg(g_csrp + beg + p);
            s = (int)(unsigned)(rec & 0xffffffffULL);
            w = __uint_as_float((unsigned)(rec >> 32));
        }
        #pragma unroll
        for (int j = 0; j < 8; j++) {
            int   ss = __shfl_sync(0xffffffffu, s, j, 8);
            float ww = __shfl_sync(0xffffffffu, w, j, 8);
            float4 v = __ldg(reinterpret_cast<const float4*>(x + (size_t)ss * FF) + chunk);
            acc.x = fmaf(v.x, ww, acc.x);
            acc.y = fmaf(v.y, ww, acc.y);
            acc.z = fmaf(v.z, ww, acc.z);
            acc.w = fmaf(v.w, ww, acc.w);
        }
    }
    reinterpret_cast<float4*>(g_aggx + (size_t)gnode * FF)[chunk] = acc;
}

// ---------------- fused projection + GRU gates (per timestep, R5 version) ---
__global__ void __launch_bounds__(256) k_gates2(int t) {
    __shared__ float ag_sh[FF][SPAD];
    __shared__ float h_sh [HH][SPAD];
    __shared__ float hr_sh[HH][SPAD];

    int tid = threadIdx.x;
    int block_base = blockIdx.x * 64;
    const float* aggx_t = g_aggx + (size_t)t * NN * FF;

    #pragma unroll
    for (int r = 0; r < 2; r++) {
        int idx = r * 256 + tid;
        int n = idx >> 3, k4 = idx & 7;
        int node = block_base + n;
        float4 v = make_float4(0.f, 0.f, 0.f, 0.f);
        if (node < NN) v = __ldg(reinterpret_cast<const float4*>(aggx_t + (size_t)node * FF) + k4);
        ag_sh[k4 * 4 + 0][n] = v.x;
        ag_sh[k4 * 4 + 1][n] = v.y;
        ag_sh[k4 * 4 + 2][n] = v.z;
        ag_sh[k4 * 4 + 3][n] = v.w;
    }
    #pragma unroll
    for (int r = 0; r < 4; r++) {
        int idx = r * 256 + tid;
        int n = idx >> 4, k4 = idx & 15;
        int node = block_base + n;
        float4 v = make_float4(0.f, 0.f, 0.f, 0.f);
        if (node < NN) v = __ldg(reinterpret_cast<const float4*>(g_h + (size_t)node * HH) + k4);
        h_sh[k4 * 4 + 0][n] = v.x;
        h_sh[k4 * 4 + 1][n] = v.y;
        h_sh[k4 * 4 + 2][n] = v.z;
        h_sh[k4 * 4 + 3][n] = v.w;
    }
    __syncthreads();

    int warp = tid >> 5, lane = tid & 31;
    int nb = warp * 8;
    int j0 = lane, j1 = lane + 32;

    float az0[8], az1[8], ar0[8], ar1[8];
    #pragma unroll
    for (int n = 0; n < 8; n++) { az0[n] = az1[n] = ar0[n] = ar1[n] = 0.f; }

    #pragma unroll
    for (int k4 = 0; k4 < FF / 4; k4++) {
        float4 wz0 = __ldg(reinterpret_cast<const float4*>(&g_Mt[0][j0][0]) + k4);
        float4 wz1 = __ldg(reinterpret_cast<const float4*>(&g_Mt[0][j1][0]) + k4);
        float4 wr0 = __ldg(reinterpret_cast<const float4*>(&g_Mt[1][j0][0]) + k4);
        float4 wr1 = __ldg(reinterpret_cast<const float4*>(&g_Mt[1][j1][0]) + k4);
        const float* pz0 = (const float*)&wz0; const float* pz1 = (const float*)&wz1;
        const float* pr0 = (const float*)&wr0; const float* pr1 = (const float*)&wr1;
        #pragma unroll
        for (int i = 0; i < 4; i++) {
            int k = k4 * 4 + i;
            float4 a0 = *reinterpret_cast<const float4*>(&ag_sh[k][nb]);
            float4 a1 = *reinterpret_cast<const float4*>(&ag_sh[k][nb + 4]);
            float aa[8] = {a0.x, a0.y, a0.z, a0.w, a1.x, a1.y, a1.z, a1.w};
            #pragma unroll
            for (int n = 0; n < 8; n++) {
                az0[n] = fmaf(aa[n], pz0[i], az0[n]);
                az1[n] = fmaf(aa[n], pz1[i], az1[n]);
                ar0[n] = fmaf(aa[n], pr0[i], ar0[n]);
                ar1[n] = fmaf(aa[n], pr1[i], ar1[n]);
            }
        }
    }
    #pragma unroll
    for (int k4 = 0; k4 < HH / 4; k4++) {
        float4 wz0 = __ldg(reinterpret_cast<const float4*>(&g_Lbt[0][j0][0]) + k4);
        float4 wz1 = __ldg(reinterpret_cast<const float4*>(&g_Lbt[0][j1][0]) + k4);
        float4 wr0 = __ldg(reinterpret_cast<const float4*>(&g_Lbt[1][j0][0]) + k4);
        float4 wr1 = __ldg(reinterpret_cast<const float4*>(&g_Lbt[1][j1][0]) + k4);
        const float* pz0 = (const float*)&wz0; const float* pz1 = (const float*)&wz1;
        const float* pr0 = (const float*)&wr0; const float* pr1 = (const float*)&wr1;
        #pragma unroll
        for (int i = 0; i < 4; i++) {
            int k = k4 * 4 + i;
            float4 a0 = *reinterpret_cast<const float4*>(&h_sh[k][nb]);
            float4 a1 = *reinterpret_cast<const float4*>(&h_sh[k][nb + 4]);
            float aa[8] = {a0.x, a0.y, a0.z, a0.w, a1.x, a1.y, a1.z, a1.w};
            #pragma unroll
            for (int n = 0; n < 8; n++) {
                az0[n] = fmaf(aa[n], pz0[i], az0[n]);
                az1[n] = fmaf(aa[n], pz1[i], az1[n]);
                ar0[n] = fmaf(aa[n], pr0[i], ar0[n]);
                ar1[n] = fmaf(aa[n], pr1[i], ar1[n]);
            }
        }
    }

    float bvz0 = __ldg(&g_bv[0][j0]), bvz1 = __ldg(&g_bv[0][j1]);
    float bvr0 = __ldg(&g_bv[1][j0]), bvr1 = __ldg(&g_bv[1][j1]);

    float Z0a[8], Z1a[8];
    #pragma unroll
    for (int n = 0; n < 8; n++) {
        Z0a[n] = sigmoidf_(az0[n] + bvz0);
        Z1a[n] = sigmoidf_(az1[n] + bvz1);
        float R0 = sigmoidf_(ar0[n] + bvr0);
        float R1 = sigmoidf_(ar1[n] + bvr1);
        hr_sh[j0][nb + n] = h_sh[j0][nb + n] * R0;
        hr_sh[j1][nb + n] = h_sh[j1][nb + n] * R1;
    }
    __syncwarp();

    float ah0[8], ah1[8];
    #pragma unroll
    for (int n = 0; n < 8; n++) { ah0[n] = ah1[n] = 0.f; }

    #pragma unroll
    for (int k4 = 0; k4 < FF / 4; k4++) {
        float4 wh0 = __ldg(reinterpret_cast<const float4*>(&g_Mt[2][j0][0]) + k4);
        float4 wh1 = __ldg(reinterpret_cast<const float4*>(&g_Mt[2][j1][0]) + k4);
        const float* p0 = (const float*)&wh0; const float* p1 = (const float*)&wh1;
        #pragma unroll
        for (int i = 0; i < 4; i++) {
            int k = k4 * 4 + i;
            float4 a0 = *reinterpret_cast<const float4*>(&ag_sh[k][nb]);
            float4 a1 = *reinterpret_cast<const float4*>(&ag_sh[k][nb + 4]);
            float aa[8] = {a0.x, a0.y, a0.z, a0.w, a1.x, a1.y, a1.z, a1.w};
            #pragma unroll
            for (int n = 0; n < 8; n++) {
                ah0[n] = fmaf(aa[n], p0[i], ah0[n]);
                ah1[n] = fmaf(aa[n], p1[i], ah1[n]);
            }
        }
    }
    #pragma unroll
    for (int k4 = 0; k4 < HH / 4; k4++) {
        float4 wh0 = __ldg(reinterpret_cast<const float4*>(&g_Lbt[2][j0][0]) + k4);
        float4 wh1 = __ldg(reinterpret_cast<const float4*>(&g_Lbt[2][j1][0]) + k4);
        const float* p0 = (const float*)&wh0; const float* p1 = (const float*)&wh1;
        #pragma unroll
        for (int i = 0; i < 4; i++) {
            int k = k4 * 4 + i;
            float4 a0 = *reinterpret_cast<const float4*>(&hr_sh[k][nb]);
            float4 a1 = *reinterpret_cast<const float4*>(&hr_sh[k][nb + 4]);
            float aa[8] = {a0.x, a0.y, a0.z, a0.w, a1.x, a1.y, a1.z, a1.w};
            #pragma unroll
            for (int n = 0; n < 8; n++) {
                ah0[n] = fmaf(aa[n], p0[i], ah0[n]);
                ah1[n] = fmaf(aa[n], p1[i], ah1[n]);
            }
        }
    }

    float bvh0 = __ldg(&g_bv[2][j0]), bvh1 = __ldg(&g_bv[2][j1]);
    #pragma unroll
    for (int n = 0; n < 8; n++) {
        int node = block_base + nb + n;
        if (node < NN) {
            float Ht0 = tanhf(ah0[n] + bvh0);
            float Ht1 = tanhf(ah1[n] + bvh1);
            float h0 = h_sh[j0][nb + n];
            float h1 = h_sh[j1][nb + n];
            g_h[(size_t)node * HH + j0] = Z0a[n] * h0 + (1.f - Z0a[n]) * Ht0;
            g_h[(size_t)node * HH + j1] = Z1a[n] * h1 + (1.f - Z1a[n]) * Ht1;
        }
    }
}

__global__ void k_out(const float* __restrict__ oW, const float* __restrict__ ob,
                      float* __restrict__ out) {
    unsigned idx = blockIdx.x * blockDim.x + threadIdx.x;
    if (idx >= (unsigned)(NN * OUTC)) return;
    int i = idx >> 4, j = idx & 15;
    const float* hr = g_h + (size_t)i * HH;
    float acc = __ldg(ob + j);
    #pragma unroll
    for (int k = 0; k < HH; k++) acc += hr[k] * __ldg(oW + k * OUTC + j);
    out[idx] = acc;
}

// ---------------- launch ----------------------------------------------------
extern "C" void kernel_launch(void* const* d_in, const int* in_sizes, int n_in,
                              void* d_out, int out_size) {
    const float* xs  = (const float*)d_in[0];
    const int*   ei  = (const int*)  d_in[1];
    const float* Wz  = (const float*)d_in[2];
    const float* bz  = (const float*)d_in[3];
    const float* Wr  = (const float*)d_in[4];
    const float* br  = (const float*)d_in[5];
    const float* Wh  = (const float*)d_in[6];
    const float* bh  = (const float*)d_in[7];
    const float* Lz  = (const float*)d_in[8];
    const float* Lzb = (const float*)d_in[9];
    const float* Lr  = (const float*)d_in[10];
    const float* Lrb = (const float*)d_in[11];
    const float* Lh  = (const float*)d_in[12];
    const float* Lhb = (const float*)d_in[13];
    const float* oW  = (const float*)d_in[14];
    const float* ob  = (const float*)d_in[15];
    float* out = (float*)d_out;

    k_prep<<<3, 256>>>(Wz, bz, Wr, br, Wh, bh, Lz, Lzb, Lr, Lrb, Lh, Lhb);
    k_clear_h<<<(NN * HH + 255) / 256, 256>>>();
    k_clear_int2<<<SCAN_BLOCKS, 256>>>();

    k_deg_all<<<TT * DEG_BPS, 256>>>(ei);
    k_dinv_all<<<SCAN_BLOCKS, 256>>>();
    k_scan_block<<<SCAN_BLOCKS, 256>>>();
    k_scan_aux<<<1, 256>>>();
    k_scan_add<<<SCAN_BLOCKS, 256>>>();
    k_place<<<TT * PLACE_BPS, 256>>>(ei);
    k_gather<<<GATH_BLOCKS, 256>>>(xs);

    for (int t = 0; t < TT; t++)
        k_gates2<<<(NN + 63) / 64, 256>>>(t);

    k_out<<<(NN * OUTC + 255) / 256, 256>>>(oW, ob, out);
}

// round 8
// speedup vs baseline: 1.5790x; 1.0114x over previous
#include <cuda_runtime.h>
#include <math.h>

#define TT 6
#define NN 50000
#define EE 800000
#define FF 32
#define HH 64
#define OUTC 16
#define SPAD 68

#define TOTN (TT * NN)                 // 300000
#define SCAN_BLOCKS 1172               // ceil(TOTN/256)
#define AUX_PER_THREAD 5               // 256*5 = 1280 >= 1172
#define DEG_BPS   3125                 // EE/256
#define PLACE_BPS 3125
#define GATH_BPS  9375                 // TOTN*8/256

// ---------------- scratch (device globals; no allocation allowed) ----------
__device__ __align__(16) float g_aggx[(size_t)TT * NN * FF];  // A_hat@X, all steps
__device__ __align__(16) float g_h   [(size_t)NN * HH];
__device__ int   g_deg [TOTN];
__device__ int   g_roff[TOTN];
__device__ int   g_cur [TOTN];
__device__ int   g_bsum[SCAN_BLOCKS];
__device__ int   g_csr [(size_t)TT * EE];
__device__ float g_dinv[TOTN];

// folded / transposed weights
__device__ __align__(16) float g_Mt [3][HH][FF];  // (W @ L_top)^T
__device__ __align__(16) float g_Lbt[3][HH][HH];  // L_bot^T
__device__ float g_bv[3][HH];

__device__ __forceinline__ float sigmoidf_(float x) {
    return 1.0f / (1.0f + __expf(-x));
}

// ---------------- prep / clears ---------------------------------------------

__global__ void k_clear_h() {
    unsigned idx = blockIdx.x * blockDim.x + threadIdx.x;
    if (idx < (unsigned)(NN * HH)) g_h[idx] = 0.0f;
}

__global__ void k_clear_int2() {
    unsigned i = blockIdx.x * blockDim.x + threadIdx.x;
    if (i < (unsigned)TOTN) { g_deg[i] = 0; g_cur[i] = 0; }
}

__global__ void k_prep(const float* __restrict__ Wz, const float* __restrict__ bz,
                       const float* __restrict__ Wr, const float* __restrict__ br,
                       const float* __restrict__ Wh, const float* __restrict__ bh,
                       const float* __restrict__ Lz, const float* __restrict__ Lzb,
                       const float* __restrict__ Lr, const float* __restrict__ Lrb,
                       const float* __restrict__ Lh, const float* __restrict__ Lhb) {
    int g = blockIdx.x;
    int t = threadIdx.x;
    const float* W  = (g == 0) ? Wz  : (g == 1) ? Wr  : Wh;
    const float* b  = (g == 0) ? bz  : (g == 1) ? br  : bh;
    const float* L  = (g == 0) ? Lz  : (g == 1) ? Lr  : Lh;
    const float* Lb = (g == 0) ? Lzb : (g == 1) ? Lrb : Lhb;

    for (int e = t; e < HH * FF; e += 256) {
        int j = e >> 5, f = e & 31;
        float s = 0.f;
        #pragma unroll 8
        for (int m = 0; m < HH; m++) s += __ldg(W + f * HH + m) * __ldg(L + m * HH + j);
        g_Mt[g][j][f] = s;
    }
    for (int e = t; e < HH * HH; e += 256) {
        int j = e >> 6, k = e & 63;
        g_Lbt[g][j][k] = __ldg(L + (HH + k) * HH + j);
    }
    if (t < HH) {
        float sb = __ldg(Lb + t);
        #pragma unroll 8
        for (int m = 0; m < HH; m++) sb += __ldg(b + m) * __ldg(L + m * HH + t);
        g_bv[g][t] = sb;
    }
}

// ---------------- degree + dinv ----------------------------------------------

__global__ void k_deg_all(const int* __restrict__ ei) {
    int t = blockIdx.x / DEG_BPS;
    unsigned e = (blockIdx.x % DEG_BPS) * 256 + threadIdx.x;
    int d = __ldg(ei + (size_t)t * 2 * EE + EE + e);
    atomicAdd(&g_deg[t * NN + d], 1);
}

__global__ void k_dinv_all() {
    unsigned i = blockIdx.x * blockDim.x + threadIdx.x;
    if (i < (unsigned)TOTN) g_dinv[i] = rsqrtf((float)(g_deg[i] + 1));
}

// ---------------- exclusive scan ----------------------------------------------

__global__ void k_scan_block() {
    __shared__ int sh[256];
    int tid = threadIdx.x;
    int i = blockIdx.x * 256 + tid;
    int v = (i < TOTN) ? g_deg[i] : 0;
    sh[tid] = v;
    __syncthreads();
    #pragma unroll
    for (int off = 1; off < 256; off <<= 1) {
        int tv = (tid >= off) ? sh[tid - off] : 0;
        __syncthreads();
        sh[tid] += tv;
        __syncthreads();
    }
    if (i < TOTN) g_roff[i] = sh[tid] - v;
    if (tid == 255) g_bsum[blockIdx.x] = sh[255];
}

__global__ void k_scan_aux() {
    __shared__ int part[256];
    int tid = threadIdx.x;
    int start = tid * AUX_PER_THREAD;
    int loc[AUX_PER_THREAD];
    int vv [AUX_PER_THREAD];
    int sum = 0;
    #pragma unroll
    for (int j = 0; j < AUX_PER_THREAD; j++) {
        int idx = start + j;
        int v = (idx < SCAN_BLOCKS) ? g_bsum[idx] : 0;
        vv[j] = v;
        sum += v;
        loc[j] = sum;
    }
    part[tid] = sum;
    __syncthreads();
    #pragma unroll
    for (int off = 1; off < 256; off <<= 1) {
        int tv = (tid >= off) ? part[tid - off] : 0;
        __syncthreads();
        part[tid] += tv;
        __syncthreads();
    }
    int prev = (tid > 0) ? part[tid - 1] : 0;
    #pragma unroll
    for (int j = 0; j < AUX_PER_THREAD; j++) {
        int idx = start + j;
        if (idx < SCAN_BLOCKS) g_bsum[idx] = prev + loc[j] - vv[j];
    }
}

__global__ void k_scan_add() {
    int i = blockIdx.x * 256 + threadIdx.x;
    if (i < TOTN) g_roff[i] += g_bsum[blockIdx.x];
}

// ---------------- CSR placement ----------------------------------------------

__global__ void k_place(const int* __restrict__ ei) {
    int t = blockIdx.x / PLACE_BPS;
    unsigned e = (blockIdx.x % PLACE_BPS) * 256 + threadIdx.x;
    const int* base = ei + (size_t)t * 2 * EE;
    int s = __ldg(base + e);
    int d = __ldg(base + EE + e);
    int i = t * NN + d;
    int pos = g_roff[i] + atomicAdd(&g_cur[i], 1);
    g_csr[pos] = s;
}

// ---------------- pull-mode gather (R5 version) ------------------------------

__global__ void k_gather(const float* __restrict__ xs) {
    unsigned idx = blockIdx.x * 256 + threadIdx.x;   // < TOTN*8
    unsigned nf = idx >> 3;          // flat (t,node)
    unsigned c  = idx & 7u;
    int t = nf / NN;
    int node = nf - t * NN;
    const float* x = xs + (size_t)t * NN * FF;

    float dd = g_dinv[nf];
    float4 acc = __ldg(reinterpret_cast<const float4*>(x + (size_t)node * FF) + c);
    float d2 = dd * dd;
    acc.x *= d2; acc.y *= d2; acc.z *= d2; acc.w *= d2;

    int beg = g_roff[nf];
    int end = beg + g_deg[nf];
    const float* dinv_t = g_dinv + t * NN;
    for (int p = beg; p < end; p++) {
        int s = __ldg(g_csr + p);
        float ns = dd * __ldg(dinv_t + s);
        float4 v = __ldg(reinterpret_cast<const float4*>(x + (size_t)s * FF) + c);
        acc.x = fmaf(v.x, ns, acc.x);
        acc.y = fmaf(v.y, ns, acc.y);
        acc.z = fmaf(v.z, ns, acc.z);
        acc.w = fmaf(v.w, ns, acc.w);
    }
    reinterpret_cast<float4*>(g_aggx + (size_t)nf * FF)[c] = acc;
}

// ---------------- fused gates, PHASE-SPLIT (low register pressure) ----------
// Block = 256 threads = 8 warps = 64 nodes. Warp: 8 nodes; lane owns cols
// j0=lane, j1=lane+32. Gates computed one at a time: Z (kept in regs),
// R (folded into hr_sh immediately), then H-tilde + combine.

// accumulate a0[8],a1[8] += A[k][nb..] * W(row j0/j1), over kcount ks.
__device__ __forceinline__ void phase_accum(const float (*__restrict__ A)[SPAD],
                                            int kcount,
                                            const float* __restrict__ W0,
                                            const float* __restrict__ W1,
                                            int nb, float* a0, float* a1) {
    #pragma unroll
    for (int k4 = 0; k4 < 16; k4++) {        // up to 64 ks
        if (k4 * 4 >= kcount) break;
        float4 w0 = __ldg(reinterpret_cast<const float4*>(W0) + k4);
        float4 w1 = __ldg(reinterpret_cast<const float4*>(W1) + k4);
        const float* p0 = (const float*)&w0;
        const float* p1 = (const float*)&w1;
        #pragma unroll
        for (int i = 0; i < 4; i++) {
            int k = k4 * 4 + i;
            float4 v0 = *reinterpret_cast<const float4*>(&A[k][nb]);
            float4 v1 = *reinterpret_cast<const float4*>(&A[k][nb + 4]);
            float aa[8] = {v0.x, v0.y, v0.z, v0.w, v1.x, v1.y, v1.z, v1.w};
            #pragma unroll
            for (int n = 0; n < 8; n++) {
                a0[n] = fmaf(aa[n], p0[i], a0[n]);
                a1[n] = fmaf(aa[n], p1[i], a1[n]);
            }
        }
    }
}

__global__ void __launch_bounds__(256, 3) k_gates2(int t) {
    __shared__ float ag_sh[FF][SPAD];
    __shared__ float h_sh [HH][SPAD];
    __shared__ float hr_sh[HH][SPAD];

    int tid = threadIdx.x;
    int block_base = blockIdx.x * 64;
    const float* aggx_t = g_aggx + (size_t)t * NN * FF;

    #pragma unroll
    for (int r = 0; r < 2; r++) {
        int idx = r * 256 + tid;
        int n = idx >> 3, k4 = idx & 7;
        int node = block_base + n;
        float4 v = make_float4(0.f, 0.f, 0.f, 0.f);
        if (node < NN) v = __ldg(reinterpret_cast<const float4*>(aggx_t + (size_t)node * FF) + k4);
        ag_sh[k4 * 4 + 0][n] = v.x;
        ag_sh[k4 * 4 + 1][n] = v.y;
        ag_sh[k4 * 4 + 2][n] = v.z;
        ag_sh[k4 * 4 + 3][n] = v.w;
    }
    #pragma unroll
    for (int r = 0; r < 4; r++) {
        int idx = r * 256 + tid;
        int n = idx >> 4, k4 = idx & 15;
        int node = block_base + n;
        float4 v = make_float4(0.f, 0.f, 0.f, 0.f);
        if (node < NN) v = __ldg(reinterpret_cast<const float4*>(g_h + (size_t)node * HH) + k4);
        h_sh[k4 * 4 + 0][n] = v.x;
        h_sh[k4 * 4 + 1][n] = v.y;
        h_sh[k4 * 4 + 2][n] = v.z;
        h_sh[k4 * 4 + 3][n] = v.w;
    }
    __syncthreads();

    int warp = tid >> 5, lane = tid & 31;
    int nb = warp * 8;
    int j0 = lane, j1 = lane + 32;

    // ---- Phase Z ----
    float a0[8], a1[8];
    #pragma unroll
    for (int n = 0; n < 8; n++) { a0[n] = a1[n] = 0.f; }
    phase_accum(ag_sh, FF, &g_Mt[0][j0][0],  &g_Mt[0][j1][0],  nb, a0, a1);
    phase_accum(h_sh,  HH, &g_Lbt[0][j0][0], &g_Lbt[0][j1][0], nb, a0, a1);

    float Z0[8], Z1[8];
    {
        float bv0 = __ldg(&g_bv[0][j0]), bv1 = __ldg(&g_bv[0][j1]);
        #pragma unroll
        for (int n = 0; n < 8; n++) {
            Z0[n] = sigmoidf_(a0[n] + bv0);
            Z1[n] = sigmoidf_(a1[n] + bv1);
        }
    }

    // ---- Phase R (consumed immediately into hr_sh) ----
    #pragma unroll
    for (int n = 0; n < 8; n++) { a0[n] = a1[n] = 0.f; }
    phase_accum(ag_sh, FF, &g_Mt[1][j0][0],  &g_Mt[1][j1][0],  nb, a0, a1);
    phase_accum(h_sh,  HH, &g_Lbt[1][j0][0], &g_Lbt[1][j1][0], nb, a0, a1);
    {
        float bv0 = __ldg(&g_bv[1][j0]), bv1 = __ldg(&g_bv[1][j1]);
        #pragma unroll
        for (int n = 0; n < 8; n++) {
            hr_sh[j0][nb + n] = h_sh[j0][nb + n] * sigmoidf_(a0[n] + bv0);
            hr_sh[j1][nb + n] = h_sh[j1][nb + n] * sigmoidf_(a1[n] + bv1);
        }
    }
    __syncwarp();

    // ---- Phase H-tilde + combine ----
    #pragma unroll
    for (int n = 0; n < 8; n++) { a0[n] = a1[n] = 0.f; }
    phase_accum(ag_sh, FF, &g_Mt[2][j0][0],  &g_Mt[2][j1][0],  nb, a0, a1);
    phase_accum(hr_sh, HH, &g_Lbt[2][j0][0], &g_Lbt[2][j1][0], nb, a0, a1);

    float bv0 = __ldg(&g_bv[2][j0]), bv1 = __ldg(&g_bv[2][j1]);
    #pragma unroll
    for (int n = 0; n < 8; n++) {
        int node = block_base + nb + n;
        if (node < NN) {
            float Ht0 = tanhf(a0[n] + bv0);
            float Ht1 = tanhf(a1[n] + bv1);
            float h0 = h_sh[j0][nb + n];
            float h1 = h_sh[j1][nb + n];
            g_h[(size_t)node * HH + j0] = Z0[n] * h0 + (1.f - Z0[n]) * Ht0;
            g_h[(size_t)node * HH + j1] = Z1[n] * h1 + (1.f - Z1[n]) * Ht1;
        }
    }
}

__global__ void k_out(const float* __restrict__ oW, const float* __restrict__ ob,
                      float* __restrict__ out) {
    unsigned idx = blockIdx.x * blockDim.x + threadIdx.x;
    if (idx >= (unsigned)(NN * OUTC)) return;
    int i = idx >> 4, j = idx & 15;
    const float* hr = g_h + (size_t)i * HH;
    float acc = __ldg(ob + j);
    #pragma unroll
    for (int k = 0; k < HH; k++) acc += hr[k] * __ldg(oW + k * OUTC + j);
    out[idx] = acc;
}

// ---------------- launch ----------------------------------------------------
extern "C" void kernel_launch(void* const* d_in, const int* in_sizes, int n_in,
                              void* d_out, int out_size) {
    const float* xs  = (const float*)d_in[0];
    const int*   ei  = (const int*)  d_in[1];
    const float* Wz  = (const float*)d_in[2];
    const float* bz  = (const float*)d_in[3];
    const float* Wr  = (const float*)d_in[4];
    const float* br  = (const float*)d_in[5];
    const float* Wh  = (const float*)d_in[6];
    const float* bh  = (const float*)d_in[7];
    const float* Lz  = (const float*)d_in[8];
    const float* Lzb = (const float*)d_in[9];
    const float* Lr  = (const float*)d_in[10];
    const float* Lrb = (const float*)d_in[11];
    const float* Lh  = (const float*)d_in[12];
    const float* Lhb = (const float*)d_in[13];
    const float* oW  = (const float*)d_in[14];
    const float* ob  = (const float*)d_in[15];
    float* out = (float*)d_out;

    k_prep<<<3, 256>>>(Wz, bz, Wr, br, Wh, bh, Lz, Lzb, Lr, Lrb, Lh, Lhb);
    k_clear_h<<<(NN * HH + 255) / 256, 256>>>();
    k_clear_int2<<<SCAN_BLOCKS, 256>>>();

    k_deg_all<<<TT * DEG_BPS, 256>>>(ei);
    k_dinv_all<<<SCAN_BLOCKS, 256>>>();
    k_scan_block<<<SCAN_BLOCKS, 256>>>();
    k_scan_aux<<<1, 256>>>();
    k_scan_add<<<SCAN_BLOCKS, 256>>>();
    k_place<<<TT * PLACE_BPS, 256>>>(ei);
    k_gather<<<GATH_BPS, 256>>>(xs);

    for (int t = 0; t < TT; t++)
        k_gates2<<<(NN + 63) / 64, 256>>>(t);

    k_out<<<(NN * OUTC + 255) / 256, 256>>>(oW, ob, out);
}